// round 5
// baseline (speedup 1.0000x reference)
// LSTM cell fused GEMM on sm_103 baseline ISA, fp16 mma.sync.m16n8k16.
//
// Phase 1 (one kernel): convert x, h, Wx, Wh fp32 -> fp16 into a 96 MB
//   __device__ scratch in one grid (DRAM stays saturated, ~38 us).
// Phase 2 (GEMM): per CTA 128 batch x (4 gates x 32 feat), all four gates
//   resident -> fused LSTM epilogue. K = 4096 (x then h) in 128-half stages
//   (two 16KB SW128 sub-tiles per operand), 3-stage cp.async pipeline
//   (192 KB smem, 1 CTA/SM, 256 thr, regs free to 255), and explicit
//   ks-level fragment double buffering to hide LDSM latency behind MMAs.

#include <cuda_runtime.h>
#include <cuda_fp16.h>
#include <cstdint>

#define DEVINL __device__ __forceinline__

constexpr int BATCH = 4096;
constexpr int SZ    = 2048;
constexpr int TM    = 128;               // batch tile
constexpr int TOG   = 32;                // per-gate feature tile
constexpr int TN    = 128;               // 4 gates * TOG
constexpr int KS    = 128;               // K halfs per stage
constexpr int NS    = (2 * SZ) / KS;     // 32 stages (16 x-phase + 16 h-phase)
constexpr int STAGES = 3;
constexpr int SUB   = 128 * 128;         // 16 KB sub-tile (128 rows x 128 B)
constexpr int ABYTES = 2 * SUB;          // 32 KB
constexpr int BBYTES = 2 * SUB;          // 32 KB
constexpr int STAGE_BYTES = ABYTES + BBYTES;   // 64 KB
constexpr int SM_BIAS = STAGES * STAGE_BYTES;  // 196608
constexpr int SMEM_TOTAL = SM_BIAS + TN * 4;   // 197120
constexpr int EPS = 130;                 // epilogue smem row stride (floats)

// fp16 scratch: [x | h | Wx | Wh], contiguous in input-concatenation order.
constexpr size_t OFF_X  = 0;
constexpr size_t OFF_H  = (size_t)BATCH * SZ;
constexpr size_t OFF_WX = OFF_H + (size_t)BATCH * SZ;
constexpr size_t OFF_WH = OFF_WX + (size_t)4 * SZ * SZ;
constexpr size_t SCRATCH_ELEMS = OFF_WH + (size_t)4 * SZ * SZ;  // 50,331,648
__device__ __half g_scratch[SCRATCH_ELEMS];

constexpr int ACT4 = BATCH * SZ / 4;     // float4 count per activation
constexpr int W4   = 4 * SZ * SZ / 4;    // float4 count per weight tensor
constexpr int TOT4 = 2 * ACT4 + 2 * W4;  // 12,582,912 (multiple of 256)

DEVINL uint32_t smem_u32(const void* p) {
  uint32_t r;
  asm("{ .reg .u64 t; cvta.to.shared.u64 t, %1; cvt.u32.u64 %0, t; }"
      : "=r"(r) : "l"(p));
  return r;
}
DEVINL uint32_t swz(uint32_t b) { return b ^ ((b >> 3) & 0x70); }

DEVINL void cp16(uint32_t dst, const void* src) {
  asm volatile("cp.async.cg.shared.global [%0], [%1], 16;"
               :: "r"(dst), "l"(src));
}
DEVINL void cp_commit() { asm volatile("cp.async.commit_group;"); }
template <int N> DEVINL void cp_wait() {
  asm volatile("cp.async.wait_group %0;" :: "n"(N));
}

DEVINL void ldsm4(uint32_t* r, uint32_t addr) {
  asm volatile(
      "ldmatrix.sync.aligned.m8n8.x4.shared.b16 {%0,%1,%2,%3}, [%4];"
      : "=r"(r[0]), "=r"(r[1]), "=r"(r[2]), "=r"(r[3]) : "r"(addr));
}
DEVINL void mma16(float* d, const uint32_t* a, const uint32_t* b) {
  asm volatile(
      "mma.sync.aligned.m16n8k16.row.col.f32.f16.f16.f32 "
      "{%0,%1,%2,%3}, {%4,%5,%6,%7}, {%8,%9}, {%0,%1,%2,%3};"
      : "+f"(d[0]), "+f"(d[1]), "+f"(d[2]), "+f"(d[3])
      : "r"(a[0]), "r"(a[1]), "r"(a[2]), "r"(a[3]), "r"(b[0]), "r"(b[1]));
}

DEVINL float sigmoidf_(float x) { return __fdividef(1.f, 1.f + __expf(-x)); }
DEVINL float tanhf_(float x) {
  float a = fabsf(x);
  float e = __expf(-2.f * a);
  return copysignf(__fdividef(1.f - e, 1.f + e), x);
}

// ---- Phase 1: single fp32 -> fp16 converter over all four tensors ----
__global__ void __launch_bounds__(256)
cvt_all_kernel(const float* __restrict__ x, const float* __restrict__ h,
               const float* __restrict__ wx, const float* __restrict__ wh) {
  int i = blockIdx.x * 256 + threadIdx.x;   // global float4 index
  const float* src;
  int base;
  if (i < ACT4)               { src = x;  base = 0; }
  else if (i < 2 * ACT4)      { src = h;  base = ACT4; }
  else if (i < 2 * ACT4 + W4) { src = wx; base = 2 * ACT4; }
  else                        { src = wh; base = 2 * ACT4 + W4; }
  float4 v = ((const float4*)src)[i - base];
  __half2* dst = (__half2*)g_scratch;
  dst[2 * (size_t)i]     = __floats2half2_rn(v.x, v.y);
  dst[2 * (size_t)i + 1] = __floats2half2_rn(v.z, v.w);
}

// ---- Phase 2: fused GEMM + LSTM epilogue ----
__global__ void __launch_bounds__(256, 1)
lstm_kernel(const float* __restrict__ c, const float* __restrict__ bx,
            const float* __restrict__ bh, float* __restrict__ out) {
  extern __shared__ char smem[];
  const uint32_t sb = smem_u32(smem);
  const int tid = threadIdx.x;
  const int lane = tid & 31;
  const int wid = tid >> 5;
  const int m0 = blockIdx.x * TM;      // batch origin
  const int o0 = blockIdx.y * TOG;     // per-gate feature origin
  const int warp_m = (wid >> 2) * 64;  // 2 warps along M
  const int warp_n = (wid & 3) * 32;   // 4 warps along N

  float* bias_sm = (float*)(smem + SM_BIAS);
  for (int i = tid; i < TN; i += 256) {
    int g = i >> 5, o = o0 + (i & 31);
    bias_sm[i] = bx[g * SZ + o] + bh[g * SZ + o];
  }

  // ldmatrix lane geometry (b16 tiles; rows are 128 B, 16 B chunks).
  const int a_r  = lane & 15;
  const int a_c  = (lane & 16) ? 16 : 0;
  const int b_r  = (lane & 7) | ((lane & 16) >> 1);
  const int b_c  = (lane & 8) ? 16 : 0;

  // Stage producer: 128 K-halfs as two 16 KB SW128 sub-tiles per operand.
  auto load_stage = [&](int s, int buf) {
    const __half* __restrict__ sa =
        g_scratch + ((s < NS / 2) ? OFF_X : OFF_H);
    const __half* __restrict__ sw =
        g_scratch + ((s < NS / 2) ? OFF_WX : OFF_WH);
    const int k0 = (s & (NS / 2 - 1)) * KS;
    const uint32_t ab = sb + buf * STAGE_BYTES;
    const uint32_t bb = ab + ABYTES;
#pragma unroll
    for (int j = 0; j < 8; ++j) {        // A: 2048 16-B chunks
      int ch = tid + j * 256;
      int sub = ch >> 10, row = (ch >> 3) & 127, cc = ch & 7;
      cp16(ab + sub * SUB + swz((uint32_t)(row * 128 + cc * 16)),
           sa + (size_t)(m0 + row) * SZ + (k0 + sub * 64 + cc * 8));
    }
#pragma unroll
    for (int j = 0; j < 8; ++j) {        // B: rows = g*32 + o_local
      int ch = tid + j * 256;
      int sub = ch >> 10, row = (ch >> 3) & 127, cc = ch & 7;
      int g = row >> 5, o = row & 31;
      cp16(bb + sub * SUB + swz((uint32_t)(row * 128 + cc * 16)),
           sw + (size_t)(g * SZ + o0 + o) * SZ + (k0 + sub * 64 + cc * 8));
    }
  };

  // Fragment loader for one k16 block (ks in [0,8)).
  auto ldfrag = [&](int ks, uint32_t af[4][4], uint32_t bq[2][4],
                    uint32_t ab, uint32_t bb) {
    const uint32_t soff = (ks >> 2) * SUB;
    const uint32_t kc = (ks & 3) * 32;
#pragma unroll
    for (int mt = 0; mt < 4; ++mt)
      ldsm4(af[mt], ab + soff +
            swz((uint32_t)((warp_m + mt * 16 + a_r) * 128 + kc + a_c)));
#pragma unroll
    for (int np = 0; np < 2; ++np)
      ldsm4(bq[np], bb + soff +
            swz((uint32_t)((warp_n + np * 16 + b_r) * 128 + kc + b_c)));
  };

  float acc[4][4][4];
#pragma unroll
  for (int i = 0; i < 4; ++i)
#pragma unroll
    for (int j = 0; j < 4; ++j)
#pragma unroll
      for (int e = 0; e < 4; ++e) acc[i][j][e] = 0.f;

  load_stage(0, 0); cp_commit();
  load_stage(1, 1); cp_commit();

  for (int s = 0; s < NS; ++s) {
    cp_wait<1>();
    __syncthreads();
    if (s + 2 < NS) load_stage(s + 2, (s + 2) % STAGES);
    cp_commit();

    const uint32_t ab = sb + (s % STAGES) * STAGE_BYTES;
    const uint32_t bb = ab + ABYTES;

    // ks-level fragment double buffer: LDSM of ks+1 overlaps MMAs of ks.
    uint32_t af[2][4][4], bq[2][2][4];
    ldfrag(0, af[0], bq[0], ab, bb);
#pragma unroll
    for (int ks = 0; ks < 8; ++ks) {
      const int cur = ks & 1, nxt = cur ^ 1;
      if (ks < 7) ldfrag(ks + 1, af[nxt], bq[nxt], ab, bb);
#pragma unroll
      for (int mt = 0; mt < 4; ++mt)
#pragma unroll
        for (int nt = 0; nt < 4; ++nt)
          mma16(acc[mt][nt], af[cur][mt], &bq[cur][nt >> 1][(nt & 1) * 2]);
    }
  }

  // Epilogue: regather all 4 gates per (b, o) through smem (reuse stage bufs).
  cp_wait<0>();
  __syncthreads();
  float* ep = (float*)smem;  // [128][EPS]
#pragma unroll
  for (int mt = 0; mt < 4; ++mt)
#pragma unroll
    for (int nt = 0; nt < 4; ++nt) {
      int row = warp_m + mt * 16 + (lane >> 2);
      int col = warp_n + nt * 8 + 2 * (lane & 3);
      ep[row * EPS + col]           = acc[mt][nt][0];
      ep[row * EPS + col + 1]       = acc[mt][nt][1];
      ep[(row + 8) * EPS + col]     = acc[mt][nt][2];
      ep[(row + 8) * EPS + col + 1] = acc[mt][nt][3];
    }
  __syncthreads();

#pragma unroll 1
  for (int p = 0; p < 16; ++p) {
    int idx = tid + p * 256;          // 128*32 outputs per CTA
    int b = idx >> 5, o = idx & 31;
    float gi = ep[b * EPS + 0 * 32 + o] + bias_sm[0 * 32 + o];
    float gf = ep[b * EPS + 1 * 32 + o] + bias_sm[1 * 32 + o];
    float go = ep[b * EPS + 2 * 32 + o] + bias_sm[2 * 32 + o];
    float gc = ep[b * EPS + 3 * 32 + o] + bias_sm[3 * 32 + o];
    size_t gidx = (size_t)(m0 + b) * SZ + (o0 + o);
    float cv = c[gidx];
    float iv = sigmoidf_(gi), fv = sigmoidf_(gf), ov = sigmoidf_(go);
    float cand = tanhf_(gc);
    float cn = fv * cv + iv * cand;
    out[gidx] = ov * tanhf_(cn);
    out[(size_t)BATCH * SZ + gidx] = cn;
  }
}

extern "C" void kernel_launch(void* const* d_in, const int* in_sizes, int n_in,
                              void* d_out, int out_size) {
  (void)in_sizes; (void)n_in; (void)out_size;
  const float* x  = (const float*)d_in[0];
  const float* h  = (const float*)d_in[1];
  const float* c  = (const float*)d_in[2];
  const float* Wx = (const float*)d_in[3];
  const float* bx = (const float*)d_in[4];
  const float* Wh = (const float*)d_in[5];
  const float* bh = (const float*)d_in[6];

  cvt_all_kernel<<<TOT4 / 256, 256>>>(x, h, Wx, Wh);

  cudaFuncSetAttribute(lstm_kernel, cudaFuncAttributeMaxDynamicSharedMemorySize,
                       SMEM_TOTAL);
  dim3 grid(BATCH / TM, SZ / TOG, 1);
  lstm_kernel<<<grid, 256, SMEM_TOTAL>>>(c, bx, bh, (float*)d_out);
}

// round 6
// speedup vs baseline: 1.1899x; 1.1899x over previous
// LSTM cell fused GEMM on sm_103 baseline ISA, fp16 mma.sync.m16n8k16.
//
// Phase 1 (one kernel): convert x, h, Wx, Wh fp32 -> fp16 into a 96 MB
//   __device__ scratch in a single grid (~38 us, DRAM-saturated).
// Phase 2 (GEMM): per CTA 128 batch x (4 gates x 32 feat), all four gates
//   resident -> fused LSTM epilogue. K = 4096 (x then h), 64-half stages,
//   3-stage cp.async pipeline (96 KB smem, 2 CTA/SM for cross-CTA latency
//   hiding). Stage ordering: ldmatrix of ks0 issued BEFORE the producer
//   cp.asyncs (volatile asm preserves source order); mma16 is non-volatile
//   so ptxas may software-pipeline MMAs across LDSM boundaries.

#include <cuda_runtime.h>
#include <cuda_fp16.h>
#include <cstdint>

#define DEVINL __device__ __forceinline__

constexpr int BATCH = 4096;
constexpr int SZ    = 2048;
constexpr int TM    = 128;               // batch tile
constexpr int TOG   = 32;                // per-gate feature tile
constexpr int TN    = 128;               // 4 gates * TOG
constexpr int KS    = 64;                // K halfs per stage (128 B rows)
constexpr int NS    = (2 * SZ) / KS;     // 64 stages
constexpr int STAGES = 3;
constexpr int ABYTES = TM * KS * 2;      // 16 KB
constexpr int BBYTES = TN * KS * 2;      // 16 KB
constexpr int STAGE_BYTES = ABYTES + BBYTES;   // 32 KB
constexpr int SM_BIAS = STAGES * STAGE_BYTES;  // 98304
constexpr int SMEM_TOTAL = SM_BIAS + TN * 4;   // 98816
constexpr int EPS = 130;                 // epilogue smem row stride (floats)

// fp16 scratch: [x | h | Wx | Wh]
constexpr size_t OFF_X  = 0;
constexpr size_t OFF_H  = (size_t)BATCH * SZ;
constexpr size_t OFF_WX = OFF_H + (size_t)BATCH * SZ;
constexpr size_t OFF_WH = OFF_WX + (size_t)4 * SZ * SZ;
constexpr size_t SCRATCH_ELEMS = OFF_WH + (size_t)4 * SZ * SZ;  // 50,331,648
__device__ __half g_scratch[SCRATCH_ELEMS];

constexpr int ACT4 = BATCH * SZ / 4;
constexpr int W4   = 4 * SZ * SZ / 4;
constexpr int TOT4 = 2 * ACT4 + 2 * W4;  // 12,582,912 (multiple of 256)

DEVINL uint32_t smem_u32(const void* p) {
  uint32_t r;
  asm("{ .reg .u64 t; cvta.to.shared.u64 t, %1; cvt.u32.u64 %0, t; }"
      : "=r"(r) : "l"(p));
  return r;
}
DEVINL uint32_t swz(uint32_t b) { return b ^ ((b >> 3) & 0x70); }

DEVINL void cp16(uint32_t dst, const void* src) {
  asm volatile("cp.async.cg.shared.global [%0], [%1], 16;"
               :: "r"(dst), "l"(src));
}
DEVINL void cp_commit() { asm volatile("cp.async.commit_group;"); }
template <int N> DEVINL void cp_wait() {
  asm volatile("cp.async.wait_group %0;" :: "n"(N));
}

// Must stay volatile: ordering vs __syncthreads / cp_wait is positional.
DEVINL void ldsm4(uint32_t* r, uint32_t addr) {
  asm volatile(
      "ldmatrix.sync.aligned.m8n8.x4.shared.b16 {%0,%1,%2,%3}, [%4];"
      : "=r"(r[0]), "=r"(r[1]), "=r"(r[2]), "=r"(r[3]) : "r"(addr));
}
// Non-volatile: pure register op; lets ptxas pipeline MMAs across LDSMs.
DEVINL void mma16(float* d, const uint32_t* a, const uint32_t* b) {
  asm("mma.sync.aligned.m16n8k16.row.col.f32.f16.f16.f32 "
      "{%0,%1,%2,%3}, {%4,%5,%6,%7}, {%8,%9}, {%0,%1,%2,%3};"
      : "+f"(d[0]), "+f"(d[1]), "+f"(d[2]), "+f"(d[3])
      : "r"(a[0]), "r"(a[1]), "r"(a[2]), "r"(a[3]), "r"(b[0]), "r"(b[1]));
}

DEVINL float sigmoidf_(float x) { return __fdividef(1.f, 1.f + __expf(-x)); }
DEVINL float tanhf_(float x) {
  float a = fabsf(x);
  float e = __expf(-2.f * a);
  return copysignf(__fdividef(1.f - e, 1.f + e), x);
}

// ---- Phase 1: single fp32 -> fp16 converter over all four tensors ----
__global__ void __launch_bounds__(256)
cvt_all_kernel(const float* __restrict__ x, const float* __restrict__ h,
               const float* __restrict__ wx, const float* __restrict__ wh) {
  int i = blockIdx.x * 256 + threadIdx.x;   // global float4 index
  const float* src;
  int base;
  if (i < ACT4)               { src = x;  base = 0; }
  else if (i < 2 * ACT4)      { src = h;  base = ACT4; }
  else if (i < 2 * ACT4 + W4) { src = wx; base = 2 * ACT4; }
  else                        { src = wh; base = 2 * ACT4 + W4; }
  float4 v = ((const float4*)src)[i - base];
  __half2* dst = (__half2*)g_scratch;
  dst[2 * (size_t)i]     = __floats2half2_rn(v.x, v.y);
  dst[2 * (size_t)i + 1] = __floats2half2_rn(v.z, v.w);
}

// ---- Phase 2: fused GEMM + LSTM epilogue ----
__global__ void __launch_bounds__(256, 2)
lstm_kernel(const float* __restrict__ c, const float* __restrict__ bx,
            const float* __restrict__ bh, float* __restrict__ out) {
  extern __shared__ char smem[];
  const uint32_t sb = smem_u32(smem);
  const int tid = threadIdx.x;
  const int lane = tid & 31;
  const int wid = tid >> 5;
  const int m0 = blockIdx.x * TM;      // batch origin
  const int o0 = blockIdx.y * TOG;     // per-gate feature origin
  const int warp_m = (wid >> 2) * 64;  // 2 warps along M
  const int warp_n = (wid & 3) * 32;   // 4 warps along N

  float* bias_sm = (float*)(smem + SM_BIAS);
  for (int i = tid; i < TN; i += 256) {
    int g = i >> 5, o = o0 + (i & 31);
    bias_sm[i] = bx[g * SZ + o] + bh[g * SZ + o];
  }

  // ldmatrix lane geometry (b16 tiles; rows are 128 B, 16 B chunks).
  const int a_r  = lane & 15;
  const int a_c  = (lane & 16) ? 16 : 0;
  const int b_r  = (lane & 7) | ((lane & 16) >> 1);
  const int b_c  = (lane & 8) ? 16 : 0;

  auto load_stage = [&](int s, int buf) {
    const __half* __restrict__ sa =
        g_scratch + ((s < NS / 2) ? OFF_X : OFF_H);
    const __half* __restrict__ sw =
        g_scratch + ((s < NS / 2) ? OFF_WX : OFF_WH);
    const int k0 = (s & (NS / 2 - 1)) * KS;
    const uint32_t ab = sb + buf * STAGE_BYTES;
    const uint32_t bb = ab + ABYTES;
#pragma unroll
    for (int j = 0; j < 4; ++j) {     // A: 128 rows x 128 B
      int ch = tid + j * 256;
      int row = ch >> 3, cc = ch & 7;
      cp16(ab + swz((uint32_t)(row * 128 + cc * 16)),
           sa + (size_t)(m0 + row) * SZ + (k0 + cc * 8));
    }
#pragma unroll
    for (int j = 0; j < 4; ++j) {     // B: rows = g*32 + o_local
      int ch = tid + j * 256;
      int row = ch >> 3, cc = ch & 7;
      int g = row >> 5, o = row & 31;
      cp16(bb + swz((uint32_t)(row * 128 + cc * 16)),
           sw + (size_t)(g * SZ + o0 + o) * SZ + (k0 + cc * 8));
    }
  };

  auto ldfrag = [&](int ks, uint32_t af[4][4], uint32_t bq[2][4],
                    uint32_t ab, uint32_t bb) {
    const uint32_t kc = (uint32_t)ks * 32;
#pragma unroll
    for (int mt = 0; mt < 4; ++mt)
      ldsm4(af[mt],
            ab + swz((uint32_t)((warp_m + mt * 16 + a_r) * 128 + kc + a_c)));
#pragma unroll
    for (int np = 0; np < 2; ++np)
      ldsm4(bq[np],
            bb + swz((uint32_t)((warp_n + np * 16 + b_r) * 128 + kc + b_c)));
  };

  auto mmablk = [&](float acc[4][4][4], uint32_t af[4][4], uint32_t bq[2][4]) {
#pragma unroll
    for (int mt = 0; mt < 4; ++mt)
#pragma unroll
      for (int nt = 0; nt < 4; ++nt)
        mma16(acc[mt][nt], af[mt], &bq[nt >> 1][(nt & 1) * 2]);
  };

  float acc[4][4][4];
#pragma unroll
  for (int i = 0; i < 4; ++i)
#pragma unroll
    for (int j = 0; j < 4; ++j)
#pragma unroll
      for (int e = 0; e < 4; ++e) acc[i][j][e] = 0.f;

  load_stage(0, 0); cp_commit();
  load_stage(1, 1); cp_commit();

  for (int s = 0; s < NS; ++s) {
    cp_wait<1>();
    __syncthreads();

    const uint32_t ab = sb + (s % STAGES) * STAGE_BYTES;
    const uint32_t bb = ab + ABYTES;
    uint32_t af[4][4], bq[2][4];

    // Fragments of ks=0 FIRST (volatile order => SASS order), so MMAs can
    // start while the producer cp.asyncs below queue into the LSU.
    ldfrag(0, af, bq, ab, bb);
    if (s + 2 < NS) load_stage(s + 2, (s + 2) % STAGES);
    cp_commit();
    mmablk(acc, af, bq);

#pragma unroll
    for (int ks = 1; ks < 4; ++ks) {
      ldfrag(ks, af, bq, ab, bb);
      mmablk(acc, af, bq);
    }
  }

  // Epilogue: regather all 4 gates per (b, o) through smem (reuse stage bufs).
  cp_wait<0>();
  __syncthreads();
  float* ep = (float*)smem;  // [128][EPS]
#pragma unroll
  for (int mt = 0; mt < 4; ++mt)
#pragma unroll
    for (int nt = 0; nt < 4; ++nt) {
      int row = warp_m + mt * 16 + (lane >> 2);
      int col = warp_n + nt * 8 + 2 * (lane & 3);
      ep[row * EPS + col]           = acc[mt][nt][0];
      ep[row * EPS + col + 1]       = acc[mt][nt][1];
      ep[(row + 8) * EPS + col]     = acc[mt][nt][2];
      ep[(row + 8) * EPS + col + 1] = acc[mt][nt][3];
    }
  __syncthreads();

#pragma unroll 1
  for (int p = 0; p < 16; ++p) {
    int idx = tid + p * 256;          // 128*32 outputs per CTA
    int b = idx >> 5, o = idx & 31;
    float gi = ep[b * EPS + 0 * 32 + o] + bias_sm[0 * 32 + o];
    float gf = ep[b * EPS + 1 * 32 + o] + bias_sm[1 * 32 + o];
    float go = ep[b * EPS + 2 * 32 + o] + bias_sm[2 * 32 + o];
    float gc = ep[b * EPS + 3 * 32 + o] + bias_sm[3 * 32 + o];
    size_t gidx = (size_t)(m0 + b) * SZ + (o0 + o);
    float cv = c[gidx];
    float iv = sigmoidf_(gi), fv = sigmoidf_(gf), ov = sigmoidf_(go);
    float cand = tanhf_(gc);
    float cn = fv * cv + iv * cand;
    out[gidx] = ov * tanhf_(cn);
    out[(size_t)BATCH * SZ + gidx] = cn;
  }
}

extern "C" void kernel_launch(void* const* d_in, const int* in_sizes, int n_in,
                              void* d_out, int out_size) {
  (void)in_sizes; (void)n_in; (void)out_size;
  const float* x  = (const float*)d_in[0];
  const float* h  = (const float*)d_in[1];
  const float* c  = (const float*)d_in[2];
  const float* Wx = (const float*)d_in[3];
  const float* bx = (const float*)d_in[4];
  const float* Wh = (const float*)d_in[5];
  const float* bh = (const float*)d_in[6];

  cvt_all_kernel<<<TOT4 / 256, 256>>>(x, h, Wx, Wh);

  cudaFuncSetAttribute(lstm_kernel, cudaFuncAttributeMaxDynamicSharedMemorySize,
                       SMEM_TOTAL);
  dim3 grid(BATCH / TM, SZ / TOG, 1);
  lstm_kernel<<<grid, 256, SMEM_TOTAL>>>(c, bx, bh, (float*)d_out);
}

// round 7
// speedup vs baseline: 1.3126x; 1.1031x over previous
// LSTM cell fused GEMM on sm_103 baseline ISA, fp16 mma.sync.m16n8k16.
//
// Phase 1: single kernel converts x,h,Wx,Wh fp32->fp16 into 96 MB scratch.
// Phase 2: per CTA 128 batch x (4 gates x 32 feat), 4 gates resident ->
//   fused LSTM epilogue. K=4096 in 64-half stages, 3 smem buffers.
//   NO __syncthreads in the mainloop: per-buffer full/empty mbarrier pairs.
//   full  (count 256): each thread cp.async's its slice then
//                      cp.async.mbarrier.arrive.noinc -> flips when the
//                      whole stage's data has LANDED in smem.
//   empty (count 8):   lane 0 of each warp arrives after the warp's last
//                      ldmatrix of that buffer -> producer may refill.
//   Warps drift up to ~2 stages; tensor pipe stays fed across boundaries.

#include <cuda_runtime.h>
#include <cuda_fp16.h>
#include <cstdint>

#define DEVINL __device__ __forceinline__

constexpr int BATCH = 4096;
constexpr int SZ    = 2048;
constexpr int TM    = 128;               // batch tile
constexpr int TOG   = 32;                // per-gate feature tile
constexpr int TN    = 128;               // 4 gates * TOG
constexpr int KS    = 64;                // K halfs per stage (128 B rows)
constexpr int NS    = (2 * SZ) / KS;     // 64 stages
constexpr int NBUF  = 3;
constexpr int ABYTES = TM * KS * 2;      // 16 KB
constexpr int BBYTES = TN * KS * 2;      // 16 KB
constexpr int STAGE_BYTES = ABYTES + BBYTES;   // 32 KB
constexpr int SM_BIAS = NBUF * STAGE_BYTES;    // 98304
constexpr int SM_MBAR = SM_BIAS + TN * 4;      // 98816
constexpr int SMEM_TOTAL = SM_MBAR + 64;       // 98880 (2 CTA/SM fits)
constexpr int EPS = 130;                 // epilogue smem row stride (floats)

// fp16 scratch: [x | h | Wx | Wh]
constexpr size_t OFF_X  = 0;
constexpr size_t OFF_H  = (size_t)BATCH * SZ;
constexpr size_t OFF_WX = OFF_H + (size_t)BATCH * SZ;
constexpr size_t OFF_WH = OFF_WX + (size_t)4 * SZ * SZ;
constexpr size_t SCRATCH_ELEMS = OFF_WH + (size_t)4 * SZ * SZ;
__device__ __half g_scratch[SCRATCH_ELEMS];

constexpr int ACT4 = BATCH * SZ / 4;
constexpr int W4   = 4 * SZ * SZ / 4;
constexpr int TOT4 = 2 * ACT4 + 2 * W4;

DEVINL uint32_t smem_u32(const void* p) {
  uint32_t r;
  asm("{ .reg .u64 t; cvta.to.shared.u64 t, %1; cvt.u32.u64 %0, t; }"
      : "=r"(r) : "l"(p));
  return r;
}
DEVINL uint32_t swz(uint32_t b) { return b ^ ((b >> 3) & 0x70); }

DEVINL void cp16(uint32_t dst, const void* src) {
  asm volatile("cp.async.cg.shared.global [%0], [%1], 16;"
               :: "r"(dst), "l"(src));
}
DEVINL void cp_arrive_noinc(uint32_t mbar) {
  asm volatile("cp.async.mbarrier.arrive.noinc.shared.b64 [%0];"
               :: "r"(mbar) : "memory");
}
DEVINL void mbar_init(uint32_t mbar, uint32_t cnt) {
  asm volatile("mbarrier.init.shared.b64 [%0], %1;" :: "r"(mbar), "r"(cnt)
               : "memory");
}
DEVINL void mbar_arrive(uint32_t mbar) {
  asm volatile("mbarrier.arrive.release.cta.shared::cta.b64 _, [%0];"
               :: "r"(mbar) : "memory");
}
DEVINL void mbar_wait(uint32_t mbar, uint32_t parity) {
  asm volatile(
      "{\n\t.reg .pred P;\n"
      "W%=:\n\t"
      "mbarrier.try_wait.parity.acquire.cta.shared::cta.b64 P, [%0], %1, 0x989680;\n\t"
      "@!P bra W%=;\n\t}"
      :: "r"(mbar), "r"(parity) : "memory");
}

// Must stay volatile: ordering vs mbarrier waits is positional.
DEVINL void ldsm4(uint32_t* r, uint32_t addr) {
  asm volatile(
      "ldmatrix.sync.aligned.m8n8.x4.shared.b16 {%0,%1,%2,%3}, [%4];"
      : "=r"(r[0]), "=r"(r[1]), "=r"(r[2]), "=r"(r[3]) : "r"(addr));
}
// Non-volatile: pure register op; ptxas may pipeline across LDSMs.
DEVINL void mma16(float* d, const uint32_t* a, const uint32_t* b) {
  asm("mma.sync.aligned.m16n8k16.row.col.f32.f16.f16.f32 "
      "{%0,%1,%2,%3}, {%4,%5,%6,%7}, {%8,%9}, {%0,%1,%2,%3};"
      : "+f"(d[0]), "+f"(d[1]), "+f"(d[2]), "+f"(d[3])
      : "r"(a[0]), "r"(a[1]), "r"(a[2]), "r"(a[3]), "r"(b[0]), "r"(b[1]));
}

DEVINL float sigmoidf_(float x) { return __fdividef(1.f, 1.f + __expf(-x)); }
DEVINL float tanhf_(float x) {
  float a = fabsf(x);
  float e = __expf(-2.f * a);
  return copysignf(__fdividef(1.f - e, 1.f + e), x);
}

// ---- Phase 1: single fp32 -> fp16 converter over all four tensors ----
__global__ void __launch_bounds__(256)
cvt_all_kernel(const float* __restrict__ x, const float* __restrict__ h,
               const float* __restrict__ wx, const float* __restrict__ wh) {
  int i = blockIdx.x * 256 + threadIdx.x;
  const float* src;
  int base;
  if (i < ACT4)               { src = x;  base = 0; }
  else if (i < 2 * ACT4)      { src = h;  base = ACT4; }
  else if (i < 2 * ACT4 + W4) { src = wx; base = 2 * ACT4; }
  else                        { src = wh; base = 2 * ACT4 + W4; }
  float4 v = ((const float4*)src)[i - base];
  __half2* dst = (__half2*)g_scratch;
  dst[2 * (size_t)i]     = __floats2half2_rn(v.x, v.y);
  dst[2 * (size_t)i + 1] = __floats2half2_rn(v.z, v.w);
}

// ---- Phase 2: fused GEMM + LSTM epilogue, mbarrier-pipelined ----
__global__ void __launch_bounds__(256, 2)
lstm_kernel(const float* __restrict__ c, const float* __restrict__ bx,
            const float* __restrict__ bh, float* __restrict__ out) {
  extern __shared__ char smem[];
  const uint32_t sb = smem_u32(smem);
  const int tid = threadIdx.x;
  const int lane = tid & 31;
  const int wid = tid >> 5;
  const int m0 = blockIdx.x * TM;
  const int o0 = blockIdx.y * TOG;
  const int warp_m = (wid >> 2) * 64;
  const int warp_n = (wid & 3) * 32;

  // mbarriers: [full0, empty0, full1, empty1, full2, empty2]
  if (tid == 0) {
#pragma unroll
    for (int b = 0; b < NBUF; ++b) {
      mbar_init(sb + SM_MBAR + b * 16, 256);     // full: one arrive per thread
      mbar_init(sb + SM_MBAR + b * 16 + 8, 8);   // empty: one per warp
    }
  }
  float* bias_sm = (float*)(smem + SM_BIAS);
  for (int i = tid; i < TN; i += 256) {
    int g = i >> 5, o = o0 + (i & 31);
    bias_sm[i] = bx[g * SZ + o] + bh[g * SZ + o];
  }
  __syncthreads();

  // ldmatrix lane geometry.
  const int a_r  = lane & 15;
  const int a_c  = (lane & 16) ? 16 : 0;
  const int b_r  = (lane & 7) | ((lane & 16) >> 1);
  const int b_c  = (lane & 8) ? 16 : 0;

  // Per-thread producer slice for one stage (4 A + 4 B cp.asyncs).
  int pstage = 0, pphase = 1;     // producer cursor (first 3 waits pass)
  int cstage = 0, cphase = 0;     // consumer cursor
  auto produce = [&](int s) {
    const __half* __restrict__ sa = g_scratch + ((s < NS / 2) ? OFF_X : OFF_H);
    const __half* __restrict__ sw = g_scratch + ((s < NS / 2) ? OFF_WX : OFF_WH);
    const int k0 = (s & (NS / 2 - 1)) * KS;
    const uint32_t mb = sb + SM_MBAR + pstage * 16;
    mbar_wait(mb + 8, (uint32_t)pphase);          // buffer free?
    const uint32_t ab = sb + pstage * STAGE_BYTES;
    const uint32_t bb = ab + ABYTES;
#pragma unroll
    for (int j = 0; j < 4; ++j) {
      int ch = tid + j * 256;
      int row = ch >> 3, cc = ch & 7;
      cp16(ab + swz((uint32_t)(row * 128 + cc * 16)),
           sa + (size_t)(m0 + row) * SZ + (k0 + cc * 8));
    }
#pragma unroll
    for (int j = 0; j < 4; ++j) {
      int ch = tid + j * 256;
      int row = ch >> 3, cc = ch & 7;
      int g = row >> 5, o = row & 31;
      cp16(bb + swz((uint32_t)(row * 128 + cc * 16)),
           sw + (size_t)(g * SZ + o0 + o) * SZ + (k0 + cc * 8));
    }
    cp_arrive_noinc(mb);                          // async arrive on full
    if (++pstage == NBUF) { pstage = 0; pphase ^= 1; }
  };

  auto ldfrag = [&](int ks, uint32_t af[4][4], uint32_t bq[2][4],
                    uint32_t ab, uint32_t bb) {
    const uint32_t kc = (uint32_t)ks * 32;
#pragma unroll
    for (int mt = 0; mt < 4; ++mt)
      ldsm4(af[mt],
            ab + swz((uint32_t)((warp_m + mt * 16 + a_r) * 128 + kc + a_c)));
#pragma unroll
    for (int np = 0; np < 2; ++np)
      ldsm4(bq[np],
            bb + swz((uint32_t)((warp_n + np * 16 + b_r) * 128 + kc + b_c)));
  };
  auto mmablk = [&](float acc[4][4][4], uint32_t af[4][4], uint32_t bq[2][4]) {
#pragma unroll
    for (int mt = 0; mt < 4; ++mt)
#pragma unroll
      for (int nt = 0; nt < 4; ++nt)
        mma16(acc[mt][nt], af[mt], &bq[nt >> 1][(nt & 1) * 2]);
  };

  float acc[4][4][4];
#pragma unroll
  for (int i = 0; i < 4; ++i)
#pragma unroll
    for (int j = 0; j < 4; ++j)
#pragma unroll
      for (int e = 0; e < 4; ++e) acc[i][j][e] = 0.f;

  produce(0);
  produce(1);

  for (int s = 0; s < NS; ++s) {
    if (s + 2 < NS) produce(s + 2);
    const uint32_t mb = sb + SM_MBAR + cstage * 16;
    mbar_wait(mb, (uint32_t)cphase);              // stage data landed?
    const uint32_t ab = sb + cstage * STAGE_BYTES;
    const uint32_t bb = ab + ABYTES;
    uint32_t af[4][4], bq[2][4];
#pragma unroll
    for (int ks = 0; ks < 4; ++ks) {
      ldfrag(ks, af, bq, ab, bb);
      if (ks == 3 && lane == 0) mbar_arrive(mb + 8);  // release buffer
      mmablk(acc, af, bq);
    }
    if (++cstage == NBUF) { cstage = 0; cphase ^= 1; }
  }

  // Epilogue: regather all 4 gates per (b, o) through smem.
  __syncthreads();
  float* ep = (float*)smem;  // [128][EPS]
#pragma unroll
  for (int mt = 0; mt < 4; ++mt)
#pragma unroll
    for (int nt = 0; nt < 4; ++nt) {
      int row = warp_m + mt * 16 + (lane >> 2);
      int col = warp_n + nt * 8 + 2 * (lane & 3);
      ep[row * EPS + col]           = acc[mt][nt][0];
      ep[row * EPS + col + 1]       = acc[mt][nt][1];
      ep[(row + 8) * EPS + col]     = acc[mt][nt][2];
      ep[(row + 8) * EPS + col + 1] = acc[mt][nt][3];
    }
  __syncthreads();

#pragma unroll 1
  for (int p = 0; p < 16; ++p) {
    int idx = tid + p * 256;
    int b = idx >> 5, o = idx & 31;
    float gi = ep[b * EPS + 0 * 32 + o] + bias_sm[0 * 32 + o];
    float gf = ep[b * EPS + 1 * 32 + o] + bias_sm[1 * 32 + o];
    float go = ep[b * EPS + 2 * 32 + o] + bias_sm[2 * 32 + o];
    float gc = ep[b * EPS + 3 * 32 + o] + bias_sm[3 * 32 + o];
    size_t gidx = (size_t)(m0 + b) * SZ + (o0 + o);
    float cv = c[gidx];
    float iv = sigmoidf_(gi), fv = sigmoidf_(gf), ov = sigmoidf_(go);
    float cand = tanhf_(gc);
    float cn = fv * cv + iv * cand;
    out[gidx] = ov * tanhf_(cn);
    out[(size_t)BATCH * SZ + gidx] = cn;
  }
}

extern "C" void kernel_launch(void* const* d_in, const int* in_sizes, int n_in,
                              void* d_out, int out_size) {
  (void)in_sizes; (void)n_in; (void)out_size;
  const float* x  = (const float*)d_in[0];
  const float* h  = (const float*)d_in[1];
  const float* c  = (const float*)d_in[2];
  const float* Wx = (const float*)d_in[3];
  const float* bx = (const float*)d_in[4];
  const float* Wh = (const float*)d_in[5];
  const float* bh = (const float*)d_in[6];

  cvt_all_kernel<<<TOT4 / 256, 256>>>(x, h, Wx, Wh);

  cudaFuncSetAttribute(lstm_kernel, cudaFuncAttributeMaxDynamicSharedMemorySize,
                       SMEM_TOTAL);
  dim3 grid(BATCH / TM, SZ / TOG, 1);
  lstm_kernel<<<grid, 256, SMEM_TOTAL>>>(c, bx, bh, (float*)d_out);
}

// round 8
// speedup vs baseline: 1.3295x; 1.0129x over previous
// LSTM cell fused GEMM on sm_103 baseline ISA, fp16 mma.sync.m16n8k16.
//
// Phase 1: single kernel converts x,h,Wx,Wh fp32->fp16 into 96 MB scratch.
// Phase 2: per CTA 128 batch x (4 gates x 32 feat) = 128x128, FOUR 64x64
//   warp tiles (2x2 grid, 128 threads). Halves LDSM read redundancy vs the
//   2x4 grid (96 -> 64 KB/stage): smem crossbar demand drops from 128 B/cyc
//   (saturated) to 94 B/cyc, unbinding the tensor pipe. K=4096 in 64-half
//   stages, 3 buffers, mbarrier producer/consumer pipeline (no mainloop
//   __syncthreads), 2 CTA/SM. Fused LSTM epilogue via smem regather.

#include <cuda_runtime.h>
#include <cuda_fp16.h>
#include <cstdint>

#define DEVINL __device__ __forceinline__

constexpr int BATCH = 4096;
constexpr int SZ    = 2048;
constexpr int TM    = 128;               // batch tile
constexpr int TOG   = 32;                // per-gate feature tile
constexpr int TN    = 128;               // 4 gates * TOG
constexpr int KS    = 64;                // K halfs per stage (128 B rows)
constexpr int NS    = (2 * SZ) / KS;     // 64 stages
constexpr int NBUF  = 3;
constexpr int NTHR  = 128;               // 4 warps
constexpr int ABYTES = TM * KS * 2;      // 16 KB
constexpr int BBYTES = TN * KS * 2;      // 16 KB
constexpr int STAGE_BYTES = ABYTES + BBYTES;   // 32 KB
constexpr int SM_BIAS = NBUF * STAGE_BYTES;    // 98304
constexpr int SM_MBAR = SM_BIAS + TN * 4;      // 98816
constexpr int SMEM_TOTAL = SM_MBAR + 64;       // 98880 (2 CTA/SM fits)
constexpr int EPS = 130;                 // epilogue smem row stride (floats)

// fp16 scratch: [x | h | Wx | Wh]
constexpr size_t OFF_X  = 0;
constexpr size_t OFF_H  = (size_t)BATCH * SZ;
constexpr size_t OFF_WX = OFF_H + (size_t)BATCH * SZ;
constexpr size_t OFF_WH = OFF_WX + (size_t)4 * SZ * SZ;
constexpr size_t SCRATCH_ELEMS = OFF_WH + (size_t)4 * SZ * SZ;
__device__ __half g_scratch[SCRATCH_ELEMS];

constexpr int ACT4 = BATCH * SZ / 4;
constexpr int W4   = 4 * SZ * SZ / 4;
constexpr int TOT4 = 2 * ACT4 + 2 * W4;

DEVINL uint32_t smem_u32(const void* p) {
  uint32_t r;
  asm("{ .reg .u64 t; cvta.to.shared.u64 t, %1; cvt.u32.u64 %0, t; }"
      : "=r"(r) : "l"(p));
  return r;
}
DEVINL uint32_t swz(uint32_t b) { return b ^ ((b >> 3) & 0x70); }

DEVINL void cp16(uint32_t dst, const void* src) {
  asm volatile("cp.async.cg.shared.global [%0], [%1], 16;"
               :: "r"(dst), "l"(src));
}
DEVINL void cp_arrive_noinc(uint32_t mbar) {
  asm volatile("cp.async.mbarrier.arrive.noinc.shared.b64 [%0];"
               :: "r"(mbar) : "memory");
}
DEVINL void mbar_init(uint32_t mbar, uint32_t cnt) {
  asm volatile("mbarrier.init.shared.b64 [%0], %1;" :: "r"(mbar), "r"(cnt)
               : "memory");
}
DEVINL void mbar_arrive(uint32_t mbar) {
  asm volatile("mbarrier.arrive.release.cta.shared::cta.b64 _, [%0];"
               :: "r"(mbar) : "memory");
}
DEVINL void mbar_wait(uint32_t mbar, uint32_t parity) {
  asm volatile(
      "{\n\t.reg .pred P;\n"
      "W%=:\n\t"
      "mbarrier.try_wait.parity.acquire.cta.shared::cta.b64 P, [%0], %1, 0x989680;\n\t"
      "@!P bra W%=;\n\t}"
      :: "r"(mbar), "r"(parity) : "memory");
}

// Volatile: ordering vs mbarrier waits is positional.
DEVINL void ldsm4(uint32_t* r, uint32_t addr) {
  asm volatile(
      "ldmatrix.sync.aligned.m8n8.x4.shared.b16 {%0,%1,%2,%3}, [%4];"
      : "=r"(r[0]), "=r"(r[1]), "=r"(r[2]), "=r"(r[3]) : "r"(addr));
}
// Non-volatile: ptxas may pipeline MMAs across LDSMs.
DEVINL void mma16(float* d, const uint32_t* a, const uint32_t* b) {
  asm("mma.sync.aligned.m16n8k16.row.col.f32.f16.f16.f32 "
      "{%0,%1,%2,%3}, {%4,%5,%6,%7}, {%8,%9}, {%0,%1,%2,%3};"
      : "+f"(d[0]), "+f"(d[1]), "+f"(d[2]), "+f"(d[3])
      : "r"(a[0]), "r"(a[1]), "r"(a[2]), "r"(a[3]), "r"(b[0]), "r"(b[1]));
}

DEVINL float sigmoidf_(float x) { return __fdividef(1.f, 1.f + __expf(-x)); }
DEVINL float tanhf_(float x) {
  float a = fabsf(x);
  float e = __expf(-2.f * a);
  return copysignf(__fdividef(1.f - e, 1.f + e), x);
}

// ---- Phase 1: single fp32 -> fp16 converter over all four tensors ----
__global__ void __launch_bounds__(256)
cvt_all_kernel(const float* __restrict__ x, const float* __restrict__ h,
               const float* __restrict__ wx, const float* __restrict__ wh) {
  int i = blockIdx.x * 256 + threadIdx.x;
  const float* src;
  int base;
  if (i < ACT4)               { src = x;  base = 0; }
  else if (i < 2 * ACT4)      { src = h;  base = ACT4; }
  else if (i < 2 * ACT4 + W4) { src = wx; base = 2 * ACT4; }
  else                        { src = wh; base = 2 * ACT4 + W4; }
  float4 v = ((const float4*)src)[i - base];
  __half2* dst = (__half2*)g_scratch;
  dst[2 * (size_t)i]     = __floats2half2_rn(v.x, v.y);
  dst[2 * (size_t)i + 1] = __floats2half2_rn(v.z, v.w);
}

// ---- Phase 2: fused GEMM + LSTM epilogue, mbarrier-pipelined ----
__global__ void __launch_bounds__(NTHR, 2)
lstm_kernel(const float* __restrict__ c, const float* __restrict__ bx,
            const float* __restrict__ bh, float* __restrict__ out) {
  extern __shared__ char smem[];
  const uint32_t sb = smem_u32(smem);
  const int tid = threadIdx.x;
  const int lane = tid & 31;
  const int wid = tid >> 5;            // 0..3
  const int m0 = blockIdx.x * TM;
  const int o0 = blockIdx.y * TOG;
  const int warp_m = (wid >> 1) * 64;  // 2 warps along M
  const int warp_n = (wid & 1) * 64;   // 2 warps along N

  if (tid == 0) {
#pragma unroll
    for (int b = 0; b < NBUF; ++b) {
      mbar_init(sb + SM_MBAR + b * 16, NTHR);    // full: one per thread
      mbar_init(sb + SM_MBAR + b * 16 + 8, 4);   // empty: one per warp
    }
  }
  float* bias_sm = (float*)(smem + SM_BIAS);
  if (tid < TN) {
    int g = tid >> 5, o = o0 + (tid & 31);
    bias_sm[tid] = bx[g * SZ + o] + bh[g * SZ + o];
  }
  __syncthreads();

  // ldmatrix lane geometry.
  const int a_r  = lane & 15;
  const int a_c  = (lane & 16) ? 16 : 0;
  const int b_r  = (lane & 7) | ((lane & 16) >> 1);
  const int b_c  = (lane & 8) ? 16 : 0;

  int pstage = 0, pphase = 1;     // producer cursor (first 3 waits pass)
  int cstage = 0, cphase = 0;     // consumer cursor
  auto produce = [&](int s) {
    const __half* __restrict__ sa = g_scratch + ((s < NS / 2) ? OFF_X : OFF_H);
    const __half* __restrict__ sw = g_scratch + ((s < NS / 2) ? OFF_WX : OFF_WH);
    const int k0 = (s & (NS / 2 - 1)) * KS;
    const uint32_t mb = sb + SM_MBAR + pstage * 16;
    mbar_wait(mb + 8, (uint32_t)pphase);          // buffer free?
    const uint32_t ab = sb + pstage * STAGE_BYTES;
    const uint32_t bb = ab + ABYTES;
#pragma unroll
    for (int j = 0; j < 8; ++j) {                 // A: 1024 16-B chunks
      int ch = tid + j * NTHR;
      int row = ch >> 3, cc = ch & 7;
      cp16(ab + swz((uint32_t)(row * 128 + cc * 16)),
           sa + (size_t)(m0 + row) * SZ + (k0 + cc * 8));
    }
#pragma unroll
    for (int j = 0; j < 8; ++j) {                 // B: rows = g*32 + o_local
      int ch = tid + j * NTHR;
      int row = ch >> 3, cc = ch & 7;
      int g = row >> 5, o = row & 31;
      cp16(bb + swz((uint32_t)(row * 128 + cc * 16)),
           sw + (size_t)(g * SZ + o0 + o) * SZ + (k0 + cc * 8));
    }
    cp_arrive_noinc(mb);
    if (++pstage == NBUF) { pstage = 0; pphase ^= 1; }
  };

  auto ldfrag = [&](int ks, uint32_t af[4][4], uint32_t bq[4][4],
                    uint32_t ab, uint32_t bb) {
    const uint32_t kc = (uint32_t)ks * 32;
#pragma unroll
    for (int mt = 0; mt < 4; ++mt)
      ldsm4(af[mt],
            ab + swz((uint32_t)((warp_m + mt * 16 + a_r) * 128 + kc + a_c)));
#pragma unroll
    for (int np = 0; np < 4; ++np)
      ldsm4(bq[np],
            bb + swz((uint32_t)((warp_n + np * 16 + b_r) * 128 + kc + b_c)));
  };
  auto mmablk = [&](float acc[4][8][4], uint32_t af[4][4], uint32_t bq[4][4]) {
#pragma unroll
    for (int mt = 0; mt < 4; ++mt)
#pragma unroll
      for (int nt = 0; nt < 8; ++nt)
        mma16(acc[mt][nt], af[mt], &bq[nt >> 1][(nt & 1) * 2]);
  };

  float acc[4][8][4];
#pragma unroll
  for (int i = 0; i < 4; ++i)
#pragma unroll
    for (int j = 0; j < 8; ++j)
#pragma unroll
      for (int e = 0; e < 4; ++e) acc[i][j][e] = 0.f;

  produce(0);
  produce(1);

  for (int s = 0; s < NS; ++s) {
    if (s + 2 < NS) produce(s + 2);
    const uint32_t mb = sb + SM_MBAR + cstage * 16;
    mbar_wait(mb, (uint32_t)cphase);
    const uint32_t ab = sb + cstage * STAGE_BYTES;
    const uint32_t bb = ab + ABYTES;
    uint32_t af[4][4], bq[4][4];
#pragma unroll
    for (int ks = 0; ks < 4; ++ks) {
      ldfrag(ks, af, bq, ab, bb);
      if (ks == 3 && lane == 0) mbar_arrive(mb + 8);  // release buffer
      mmablk(acc, af, bq);
    }
    if (++cstage == NBUF) { cstage = 0; cphase ^= 1; }
  }

  // Epilogue: regather all 4 gates per (b, o) through smem.
  __syncthreads();
  float* ep = (float*)smem;  // [128][EPS]
#pragma unroll
  for (int mt = 0; mt < 4; ++mt)
#pragma unroll
    for (int nt = 0; nt < 8; ++nt) {
      int row = warp_m + mt * 16 + (lane >> 2);
      int col = warp_n + nt * 8 + 2 * (lane & 3);
      ep[row * EPS + col]           = acc[mt][nt][0];
      ep[row * EPS + col + 1]       = acc[mt][nt][1];
      ep[(row + 8) * EPS + col]     = acc[mt][nt][2];
      ep[(row + 8) * EPS + col + 1] = acc[mt][nt][3];
    }
  __syncthreads();

#pragma unroll 1
  for (int p = 0; p < 32; ++p) {
    int idx = tid + p * NTHR;         // 128*32 outputs per CTA
    int b = idx >> 5, o = idx & 31;
    float gi = ep[b * EPS + 0 * 32 + o] + bias_sm[0 * 32 + o];
    float gf = ep[b * EPS + 1 * 32 + o] + bias_sm[1 * 32 + o];
    float go = ep[b * EPS + 2 * 32 + o] + bias_sm[2 * 32 + o];
    float gc = ep[b * EPS + 3 * 32 + o] + bias_sm[3 * 32 + o];
    size_t gidx = (size_t)(m0 + b) * SZ + (o0 + o);
    float cv = c[gidx];
    float iv = sigmoidf_(gi), fv = sigmoidf_(gf), ov = sigmoidf_(go);
    float cand = tanhf_(gc);
    float cn = fv * cv + iv * cand;
    out[gidx] = ov * tanhf_(cn);
    out[(size_t)BATCH * SZ + gidx] = cn;
  }
}

extern "C" void kernel_launch(void* const* d_in, const int* in_sizes, int n_in,
                              void* d_out, int out_size) {
  (void)in_sizes; (void)n_in; (void)out_size;
  const float* x  = (const float*)d_in[0];
  const float* h  = (const float*)d_in[1];
  const float* c  = (const float*)d_in[2];
  const float* Wx = (const float*)d_in[3];
  const float* bx = (const float*)d_in[4];
  const float* Wh = (const float*)d_in[5];
  const float* bh = (const float*)d_in[6];

  cvt_all_kernel<<<TOT4 / 256, 256>>>(x, h, Wx, Wh);

  cudaFuncSetAttribute(lstm_kernel, cudaFuncAttributeMaxDynamicSharedMemorySize,
                       SMEM_TOTAL);
  dim3 grid(BATCH / TM, SZ / TOG, 1);
  lstm_kernel<<<grid, NTHR, SMEM_TOTAL>>>(c, bx, bh, (float*)d_out);
}